// round 10
// baseline (speedup 1.0000x reference)
#include <cuda_runtime.h>
#include <cuda_bf16.h>
#include <cstdint>

#define DD 128
#define MAX_N 100000
#define MAX_E 1600000
#define TILE_R 64
#define WS_STRIDE 132   // W tile row stride (floats), float4-aligned
#define AS_STRIDE 132   // A tile row stride (floats), float4-aligned

#define BAR_SYNC(id)   asm volatile("bar.sync %0, 256;"   :: "r"(id) : "memory")
#define BAR_ARRIVE(id) asm volatile("bar.arrive %0, 256;" :: "r"(id) : "memory")

// Scratch (device globals — no allocation allowed)
__device__ float g_h[(size_t)MAX_N * DD];
__device__ float g_h2[(size_t)MAX_N * DD];
__device__ int   g_degi[MAX_N];
__device__ int   g_off[MAX_N + 1];
__device__ int   g_cursor[MAX_N];
__device__ int   g_bsum[1024];
__device__ int   g_csr[MAX_E];

// ---------------------------------------------------------------------------
// h[n][:] = emb[annotation[n]][:]  (warp per node) ; also zeroes degi
__global__ void embed_kernel(const int* __restrict__ ann,
                             const float4* __restrict__ emb,
                             float4* __restrict__ h,
                             int* __restrict__ degi, int N) {
    int gid = blockIdx.x * blockDim.x + threadIdx.x;
    if (gid < N) degi[gid] = 0;
    int n = gid >> 5;
    int lane = gid & 31;
    if (n >= N) return;
    int a = __ldg(ann + n);
    h[(size_t)n * 32 + lane] = __ldg(emb + (size_t)a * 32 + lane);
}

__global__ void degi_kernel(const int* __restrict__ dst, int* __restrict__ degi, int E) {
    int e = blockIdx.x * blockDim.x + threadIdx.x;
    if (e < E) atomicAdd(degi + dst[e], 1);
}

// Block-local exclusive scan (Hillis-Steele in smem), emits block sums
__global__ void scan1_kernel(const int* __restrict__ degi, int* __restrict__ off,
                             int* __restrict__ bsum, int N) {
    __shared__ int s[256];
    int t = threadIdx.x;
    int i = blockIdx.x * 256 + t;
    int v = (i < N) ? degi[i] : 0;
    s[t] = v;
    __syncthreads();
#pragma unroll
    for (int d = 1; d < 256; d <<= 1) {
        int add = (t >= d) ? s[t - d] : 0;
        __syncthreads();
        s[t] += add;
        __syncthreads();
    }
    if (i < N) off[i] = s[t] - v;            // exclusive within block
    if (t == 255) bsum[blockIdx.x] = s[255]; // block total
}

// Per-block: prefix = sum(bsum[0..b)), finalize off and cursor in one pass
__global__ void scan23_kernel(int* __restrict__ off, int* __restrict__ cursor,
                              const int* __restrict__ bsum, int N, int E) {
    __shared__ int s[256];
    int t = threadIdx.x;
    int b = blockIdx.x;
    int acc = 0;
    for (int j = t; j < b; j += 256) acc += bsum[j];
    s[t] = acc;
    __syncthreads();
#pragma unroll
    for (int d = 128; d > 0; d >>= 1) {
        if (t < d) s[t] += s[t + d];
        __syncthreads();
    }
    int prefix = s[0];
    int i = b * 256 + t;
    if (i < N) {
        int o = off[i] + prefix;
        off[i] = o;
        cursor[i] = o;
    }
    if (i == 0) off[N] = E;
}

__global__ void place_kernel(const int* __restrict__ src, const int* __restrict__ dst,
                             int* __restrict__ cursor, int* __restrict__ csr, int E) {
    int e = blockIdx.x * blockDim.x + threadIdx.x;
    if (e >= E) return;
    int pos = atomicAdd(cursor + dst[e], 1);
    csr[pos] = src[e];
}

// ---------------------------------------------------------------------------
// Warp-specialized fused layer: warps 0-3 gather (producer), warps 4-7 GEMM
// (consumer), double-buffered A tile, named-barrier handshake.
// Barriers: full0=1, full1=2 (producers arrive, consumers sync)
//           empty0=3, empty1=4 (consumers arrive, producers sync)
__global__ __launch_bounds__(256, 1)
void fused_layer_ws_kernel(const float4* __restrict__ hin,
                           const int* __restrict__ off,
                           const int* __restrict__ csr,
                           const float* __restrict__ W,
                           const float* __restrict__ bias,
                           float* __restrict__ hout, int N, int ntiles) {
    extern __shared__ float sh[];
    float* Wsh  = sh;                           // DD x WS_STRIDE
    float* AshB[2];
    AshB[0] = sh + DD * WS_STRIDE;              // TILE_R x AS_STRIDE
    AshB[1] = AshB[0] + TILE_R * AS_STRIDE;

    int tx  = threadIdx.x & 31;
    int wid = threadIdx.x >> 5;
    int tid = threadIdx.x;

    // ---- Load W once (all 256 threads) ----
    {
        const float4* Wg = (const float4*)W;
#pragma unroll
        for (int j = 0; j < (DD * DD / 4) / 256; j++) {
            int idx = tid + j * 256;            // = k*32 + c4
            int k  = idx >> 5;
            int c4 = idx & 31;
            *(float4*)&Wsh[k * WS_STRIDE + c4 * 4] = __ldg(Wg + idx);
        }
    }
    __syncthreads();

    if (wid < 4) {
        // ================= PRODUCER: gather =================
        int pw = wid;                           // 0..3
        int it = 0;
        for (int tile = blockIdx.x; tile < ntiles; tile += gridDim.x, it++) {
            int buf = it & 1;
            if (it >= 2) BAR_SYNC(3 + buf);     // wait consumers freed this buf
            float* Ash = AshB[buf];
            int r0 = tile * TILE_R;
#pragma unroll 1
            for (int rr = 0; rr < 16; rr++) {
                int row = rr * 4 + pw;          // 0..63
                int n = r0 + row;
                float4 acc = make_float4(0.f, 0.f, 0.f, 0.f);
                if (n < N) {
                    int beg = __ldg(off + n);
                    int end = __ldg(off + n + 1);
                    acc = __ldg(hin + (size_t)n * 32 + tx);     // self
                    int i = beg;
                    for (; i + 8 <= end; i += 8) {
                        int s[8];
#pragma unroll
                        for (int j = 0; j < 8; j++) s[j] = __ldg(csr + i + j);
                        float4 v[8];
#pragma unroll
                        for (int j = 0; j < 8; j++)
                            v[j] = __ldg(hin + (size_t)s[j] * 32 + tx);
#pragma unroll
                        for (int j = 0; j < 8; j++) {
                            acc.x += v[j].x; acc.y += v[j].y;
                            acc.z += v[j].z; acc.w += v[j].w;
                        }
                    }
                    for (; i < end; i++) {
                        int s = __ldg(csr + i);
                        float4 v = __ldg(hin + (size_t)s * 32 + tx);
                        acc.x += v.x; acc.y += v.y; acc.z += v.z; acc.w += v.w;
                    }
                }
                *(float4*)&Ash[row * AS_STRIDE + tx * 4] = acc;
            }
            BAR_ARRIVE(1 + buf);                // publish full
        }
    } else {
        // ================= CONSUMER: GEMM + epilogue =================
        int cw = wid - 4;                       // 0..3 -> rows 4i+cw
        float4 b4 = __ldg((const float4*)bias + tx);
        int it = 0;
        for (int tile = blockIdx.x; tile < ntiles; tile += gridDim.x, it++) {
            int buf = it & 1;
            BAR_SYNC(1 + buf);                  // wait buf full
            float* Ash = AshB[buf];
            int r0 = tile * TILE_R;

            unsigned long long acc2[16][2];
#pragma unroll
            for (int i = 0; i < 16; i++) { acc2[i][0] = 0ULL; acc2[i][1] = 0ULL; }

#pragma unroll 4
            for (int k = 0; k < DD; k++) {
                float4 wv = *(const float4*)&Wsh[k * WS_STRIDE + tx * 4];
                unsigned long long w2a, w2b;
                asm("mov.b64 %0, {%1,%2};" : "=l"(w2a) : "f"(wv.x), "f"(wv.y));
                asm("mov.b64 %0, {%1,%2};" : "=l"(w2b) : "f"(wv.z), "f"(wv.w));
#pragma unroll
                for (int i = 0; i < 16; i++) {
                    float a = Ash[(i * 4 + cw) * AS_STRIDE + k];
                    unsigned long long a2;
                    asm("mov.b64 %0, {%1,%1};" : "=l"(a2) : "f"(a));
                    asm("fma.rn.f32x2 %0, %1, %2, %0;"
                        : "+l"(acc2[i][0]) : "l"(a2), "l"(w2a));
                    asm("fma.rn.f32x2 %0, %1, %2, %0;"
                        : "+l"(acc2[i][1]) : "l"(a2), "l"(w2b));
                }
            }
            BAR_ARRIVE(3 + buf);                // done reading buf

#pragma unroll
            for (int i = 0; i < 16; i++) {
                int row = r0 + i * 4 + cw;
                if (row < N) {
                    int deg = __ldg(off + row + 1) - __ldg(off + row);
                    float invr = 1.0f / (float)(deg + 1);
                    unsigned int l0, h0, l1, h1;
                    asm("mov.b64 {%0,%1}, %2;" : "=r"(l0), "=r"(h0) : "l"(acc2[i][0]));
                    asm("mov.b64 {%0,%1}, %2;" : "=r"(l1), "=r"(h1) : "l"(acc2[i][1]));
                    float4 o;
                    o.x = fmaxf(__uint_as_float(l0) * invr + b4.x, 0.0f);
                    o.y = fmaxf(__uint_as_float(h0) * invr + b4.y, 0.0f);
                    o.z = fmaxf(__uint_as_float(l1) * invr + b4.z, 0.0f);
                    o.w = fmaxf(__uint_as_float(h1) * invr + b4.w, 0.0f);
                    *(float4*)(hout + (size_t)row * DD + tx * 4) = o;
                }
            }
        }
    }
}

// ---------------------------------------------------------------------------
extern "C" void kernel_launch(void* const* d_in, const int* in_sizes, int n_in,
                              void* d_out, int out_size) {
    const int*   ann = (const int*)d_in[0];
    const int*   src = (const int*)d_in[1];
    const int*   dst = (const int*)d_in[2];
    const float* emb = (const float*)d_in[3];
    const float* Ws  = (const float*)d_in[4];
    const float* bs  = (const float*)d_in[5];

    int N = in_sizes[0];
    int E = in_sizes[1];
    int L = in_sizes[4] / (DD * DD);

    float *hA, *hB;
    int *degi, *off, *cursor, *bsum, *csr;
    cudaGetSymbolAddress((void**)&hA,     g_h);
    cudaGetSymbolAddress((void**)&hB,     g_h2);
    cudaGetSymbolAddress((void**)&degi,   g_degi);
    cudaGetSymbolAddress((void**)&off,    g_off);
    cudaGetSymbolAddress((void**)&cursor, g_cursor);
    cudaGetSymbolAddress((void**)&bsum,   g_bsum);
    cudaGetSymbolAddress((void**)&csr,    g_csr);
    float* out = (float*)d_out;

    int nb = (N + 255) / 256;

    // 1) h0 = emb[annotation]  (+ zero degi)
    {
        long long t = (long long)N * 32;
        embed_kernel<<<(unsigned)((t + 255) / 256), 256>>>(ann, (const float4*)emb,
                                                           (float4*)hA, degi, N);
    }
    // 2-5) CSR build
    degi_kernel<<<(E + 255) / 256, 256>>>(dst, degi, E);
    scan1_kernel<<<nb, 256>>>(degi, off, bsum, N);
    scan23_kernel<<<nb, 256>>>(off, cursor, bsum, N, E);
    place_kernel<<<(E + 255) / 256, 256>>>(src, dst, cursor, csr, E);

    size_t shbytes = (size_t)(DD * WS_STRIDE + 2 * TILE_R * AS_STRIDE) * sizeof(float);
    cudaFuncSetAttribute(fused_layer_ws_kernel,
                         cudaFuncAttributeMaxDynamicSharedMemorySize, (int)shbytes);

    int ntiles = (N + TILE_R - 1) / TILE_R;
    int grid = 148;
    if (grid > ntiles) grid = ntiles;

    float* cur = hA;
    float* nxt = hB;
    for (int l = 0; l < L; l++) {
        float* dstbuf = (l == L - 1) ? out : nxt;
        fused_layer_ws_kernel<<<grid, 256, shbytes>>>((const float4*)cur, off, csr,
                                                      Ws + (size_t)l * DD * DD,
                                                      bs + (size_t)l * DD,
                                                      dstbuf, N, ntiles);
        float* t = cur; cur = nxt; nxt = t;
    }
}

// round 12
// speedup vs baseline: 2.1856x; 2.1856x over previous
#include <cuda_runtime.h>
#include <cuda_bf16.h>
#include <cstdint>

#define DD 128
#define MAX_N 100000
#define MAX_E 1600000
#define TILE_R 64
#define AS_STRIDE 132      // A tile row stride (floats)

// Fragment-ordered W buffers: 16 k-steps x 16 n-blocks x 32 lanes x 2 regs
#define WFRAG_FLOATS (16 * 16 * 32 * 2)   // 16384 floats = 64KB each

// ===================== scratch =====================
__device__ float g_h[(size_t)MAX_N * DD];
__device__ float g_agg[(size_t)MAX_N * DD];
__device__ int   g_degi[MAX_N];
__device__ int   g_off[MAX_N + 1];
__device__ int   g_cursor[MAX_N];
__device__ int   g_bsum[1024];
__device__ int   g_csr[MAX_E];

// ===================== CSR build + embed (proven R6 pieces) =====================
__global__ void embed_kernel(const int* __restrict__ ann,
                             const float4* __restrict__ emb,
                             float4* __restrict__ h,
                             int* __restrict__ degi, int N) {
    int gid = blockIdx.x * blockDim.x + threadIdx.x;
    if (gid < N) degi[gid] = 0;
    int n = gid >> 5;
    int lane = gid & 31;
    if (n >= N) return;
    int a = __ldg(ann + n);
    h[(size_t)n * 32 + lane] = __ldg(emb + (size_t)a * 32 + lane);
}

__global__ void degi_kernel(const int* __restrict__ dst, int* __restrict__ degi, int E) {
    int e = blockIdx.x * blockDim.x + threadIdx.x;
    if (e < E) atomicAdd(degi + dst[e], 1);
}

__global__ void scan1_kernel(const int* __restrict__ degi, int* __restrict__ off,
                             int* __restrict__ bsum, int N) {
    __shared__ int s[256];
    int t = threadIdx.x;
    int i = blockIdx.x * 256 + t;
    int v = (i < N) ? degi[i] : 0;
    s[t] = v;
    __syncthreads();
#pragma unroll
    for (int d = 1; d < 256; d <<= 1) {
        int add = (t >= d) ? s[t - d] : 0;
        __syncthreads();
        s[t] += add;
        __syncthreads();
    }
    if (i < N) off[i] = s[t] - v;
    if (t == 255) bsum[blockIdx.x] = s[255];
}

__global__ void scan23_kernel(int* __restrict__ off, int* __restrict__ cursor,
                              const int* __restrict__ bsum, int N, int E) {
    __shared__ int s[256];
    int t = threadIdx.x;
    int b = blockIdx.x;
    int acc = 0;
    for (int j = t; j < b; j += 256) acc += bsum[j];
    s[t] = acc;
    __syncthreads();
#pragma unroll
    for (int d = 128; d > 0; d >>= 1) {
        if (t < d) s[t] += s[t + d];
        __syncthreads();
    }
    int prefix = s[0];
    int i = b * 256 + t;
    if (i < N) {
        int o = off[i] + prefix;
        off[i] = o;
        cursor[i] = o;
    }
    if (i == 0) off[N] = E;
}

__global__ void place_kernel(const int* __restrict__ src, const int* __restrict__ dst,
                             int* __restrict__ cursor, int* __restrict__ csr, int E) {
    int e = blockIdx.x * blockDim.x + threadIdx.x;
    if (e >= E) return;
    int pos = atomicAdd(cursor + dst[e], 1);
    csr[pos] = src[e];
}

__global__ void gather_kernel(const float4* __restrict__ h,
                              float4* __restrict__ agg,
                              const int* __restrict__ off,
                              const int* __restrict__ csr, int N) {
    int gid = blockIdx.x * blockDim.x + threadIdx.x;
    int n = gid >> 5;
    int lane = gid & 31;
    if (n >= N) return;
    int beg = __ldg(off + n);
    int end = __ldg(off + n + 1);
    float4 acc = __ldg(h + (size_t)n * 32 + lane);
    int i = beg;
    for (; i + 4 <= end; i += 4) {
        int s0 = __ldg(csr + i);
        int s1 = __ldg(csr + i + 1);
        int s2 = __ldg(csr + i + 2);
        int s3 = __ldg(csr + i + 3);
        float4 v0 = __ldg(h + (size_t)s0 * 32 + lane);
        float4 v1 = __ldg(h + (size_t)s1 * 32 + lane);
        float4 v2 = __ldg(h + (size_t)s2 * 32 + lane);
        float4 v3 = __ldg(h + (size_t)s3 * 32 + lane);
        acc.x += v0.x + v1.x + v2.x + v3.x;
        acc.y += v0.y + v1.y + v2.y + v3.y;
        acc.z += v0.z + v1.z + v2.z + v3.z;
        acc.w += v0.w + v1.w + v2.w + v3.w;
    }
    for (; i < end; i++) {
        int s = __ldg(csr + i);
        float4 v = __ldg(h + (size_t)s * 32 + lane);
        acc.x += v.x; acc.y += v.y; acc.z += v.z; acc.w += v.w;
    }
    agg[(size_t)n * 32 + lane] = acc;
}

// ===================== 3xTF32 mma.sync layer GEMM =====================
// out[r][:] = relu( (agg[r][:] / (deg+1)) @ W + b )
// Persistent (grid=148): W split hi/lo once into fragment-ordered smem, then
// per 64-row tile: load A raw, 3-pass m16n8k8 tf32 mma, epilogue.
// Warp (wid): wm = wid&3 -> rows 16*wm..+15 ; wn = wid>>2 -> cols 64*wn..+63.

#define CVT_TF32(u, f) asm("cvt.rna.tf32.f32 %0, %1;" : "=r"(u) : "f"(f))

#define MMA_TF32(C, A0, A1, A2, A3, B0, B1)                                   \
    asm volatile("mma.sync.aligned.m16n8k8.row.col.f32.tf32.tf32.f32 "        \
                 "{%0,%1,%2,%3}, {%4,%5,%6,%7}, {%8,%9}, {%0,%1,%2,%3};"      \
                 : "+f"((C)[0]), "+f"((C)[1]), "+f"((C)[2]), "+f"((C)[3])     \
                 : "r"(A0), "r"(A1), "r"(A2), "r"(A3), "r"(B0), "r"(B1))

__global__ __launch_bounds__(256, 1)
void mma_layer_kernel(const float4* __restrict__ agg,
                      const int* __restrict__ off,
                      const float* __restrict__ W,
                      const float* __restrict__ bias,
                      float* __restrict__ out, int N, int ntiles) {
    extern __shared__ float sh[];
    float* Hf  = sh;                         // hi fragments (tf32 bits as float)
    float* Lf  = sh + WFRAG_FLOATS;          // lo fragments
    float* Ash = sh + 2 * WFRAG_FLOATS;      // TILE_R x AS_STRIDE raw fp32

    int tid  = threadIdx.x;
    int lane = tid & 31;
    int wid  = tid >> 5;
    int tig  = lane & 3;                     // thread-in-group (k)
    int gr   = lane >> 2;                    // group (row / col)
    int wm   = wid & 3;                      // m-group
    int wn   = wid >> 2;                     // n-half

    // ---- Prep W fragments (once per block) ----
    // idx = (s*16 + nblk)*32 + l ; frag regs: b0=W[8s+tg][8nblk+g], b1=W[8s+tg+4][...]
    for (int idx = tid; idx < 16 * 16 * 32; idx += 256) {
        int l    = idx & 31;
        int nblk = (idx >> 5) & 15;
        int s    = idx >> 9;
        int tg = l & 3, g = l >> 2;
        int k0 = 8 * s + tg;
        int c  = 8 * nblk + g;
        float w0 = __ldg(W + k0 * DD + c);
        float w1 = __ldg(W + (k0 + 4) * DD + c);
        uint32_t h0, h1;
        CVT_TF32(h0, w0);
        CVT_TF32(h1, w1);
        float l0 = w0 - __uint_as_float(h0);
        float l1 = w1 - __uint_as_float(h1);
        uint32_t l0t, l1t;
        CVT_TF32(l0t, l0);
        CVT_TF32(l1t, l1);
        Hf[idx * 2 + 0] = __uint_as_float(h0);
        Hf[idx * 2 + 1] = __uint_as_float(h1);
        Lf[idx * 2 + 0] = __uint_as_float(l0t);
        Lf[idx * 2 + 1] = __uint_as_float(l1t);
    }
    __syncthreads();

    for (int tile = blockIdx.x; tile < ntiles; tile += gridDim.x) {
        int r0 = tile * TILE_R;

        // ---- Load A tile raw (2048 float4 / 256 threads = 8 each) ----
#pragma unroll
        for (int j = 0; j < 8; j++) {
            int idx = tid + j * 256;
            int row = idx >> 5;
            int c4  = idx & 31;
            float4 v = make_float4(0.f, 0.f, 0.f, 0.f);
            if (r0 + row < N)
                v = __ldg(agg + (size_t)(r0 + row) * 32 + c4);
            *(float4*)&Ash[row * AS_STRIDE + c4 * 4] = v;
        }
        __syncthreads();

        // ---- MMA mainloop ----
        float c[8][4];
#pragma unroll
        for (int j = 0; j < 8; j++)
#pragma unroll
            for (int q = 0; q < 4; q++) c[j][q] = 0.0f;

#pragma unroll 2
        for (int s = 0; s < 16; s++) {
            int k0 = 8 * s;
            int ra = (16 * wm + gr) * AS_STRIDE;
            int rb = (16 * wm + gr + 8) * AS_STRIDE;
            float a0 = Ash[ra + k0 + tig];
            float a1 = Ash[rb + k0 + tig];
            float a2 = Ash[ra + k0 + tig + 4];
            float a3 = Ash[rb + k0 + tig + 4];
            uint32_t ah[4], al[4];
            CVT_TF32(ah[0], a0);
            CVT_TF32(ah[1], a1);
            CVT_TF32(ah[2], a2);
            CVT_TF32(ah[3], a3);
            al[0] = __float_as_uint(a0 - __uint_as_float(ah[0]));
            al[1] = __float_as_uint(a1 - __uint_as_float(ah[1]));
            al[2] = __float_as_uint(a2 - __uint_as_float(ah[2]));
            al[3] = __float_as_uint(a3 - __uint_as_float(ah[3]));
#pragma unroll
            for (int j = 0; j < 8; j++) {
                int nblk = wn * 8 + j;
                int fo = ((s * 16 + nblk) * 32 + lane) * 2;
                float2 wh = *(const float2*)&Hf[fo];
                float2 wl = *(const float2*)&Lf[fo];
                uint32_t wh0 = __float_as_uint(wh.x), wh1 = __float_as_uint(wh.y);
                uint32_t wl0 = __float_as_uint(wl.x), wl1 = __float_as_uint(wl.y);
                MMA_TF32(c[j], ah[0], ah[1], ah[2], ah[3], wh0, wh1);
                MMA_TF32(c[j], ah[0], ah[1], ah[2], ah[3], wl0, wl1);
                MMA_TF32(c[j], al[0], al[1], al[2], al[3], wh0, wh1);
            }
        }
        __syncthreads();   // all warps done reading Ash

        // ---- Epilogue ----
        int rowA = r0 + 16 * wm + gr;
        int rowB = rowA + 8;
        float invA = 0.f, invB = 0.f;
        if (rowA < N)
            invA = 1.0f / (float)(__ldg(off + rowA + 1) - __ldg(off + rowA) + 1);
        if (rowB < N)
            invB = 1.0f / (float)(__ldg(off + rowB + 1) - __ldg(off + rowB) + 1);
#pragma unroll
        for (int j = 0; j < 8; j++) {
            int col = wn * 64 + j * 8 + 2 * tig;
            float2 b2 = __ldg((const float2*)(bias + col));
            if (rowA < N) {
                float2 o;
                o.x = fmaxf(c[j][0] * invA + b2.x, 0.0f);
                o.y = fmaxf(c[j][1] * invA + b2.y, 0.0f);
                *(float2*)(out + (size_t)rowA * DD + col) = o;
            }
            if (rowB < N) {
                float2 o;
                o.x = fmaxf(c[j][2] * invB + b2.x, 0.0f);
                o.y = fmaxf(c[j][3] * invB + b2.y, 0.0f);
                *(float2*)(out + (size_t)rowB * DD + col) = o;
            }
        }
    }
}

// ---------------------------------------------------------------------------
extern "C" void kernel_launch(void* const* d_in, const int* in_sizes, int n_in,
                              void* d_out, int out_size) {
    const int*   ann = (const int*)d_in[0];
    const int*   src = (const int*)d_in[1];
    const int*   dst = (const int*)d_in[2];
    const float* emb = (const float*)d_in[3];
    const float* Ws  = (const float*)d_in[4];
    const float* bs  = (const float*)d_in[5];

    int N = in_sizes[0];
    int E = in_sizes[1];
    int L = in_sizes[4] / (DD * DD);

    float *h, *agg;
    int *degi, *off, *cursor, *bsum, *csr;
    cudaGetSymbolAddress((void**)&h,      g_h);
    cudaGetSymbolAddress((void**)&agg,    g_agg);
    cudaGetSymbolAddress((void**)&degi,   g_degi);
    cudaGetSymbolAddress((void**)&off,    g_off);
    cudaGetSymbolAddress((void**)&cursor, g_cursor);
    cudaGetSymbolAddress((void**)&bsum,   g_bsum);
    cudaGetSymbolAddress((void**)&csr,    g_csr);
    float* out = (float*)d_out;

    int nb = (N + 255) / 256;

    {
        long long t = (long long)N * 32;
        embed_kernel<<<(unsigned)((t + 255) / 256), 256>>>(ann, (const float4*)emb,
                                                           (float4*)h, degi, N);
    }
    degi_kernel<<<(E + 255) / 256, 256>>>(dst, degi, E);
    scan1_kernel<<<nb, 256>>>(degi, off, bsum, N);
    scan23_kernel<<<nb, 256>>>(off, cursor, bsum, N, E);
    place_kernel<<<(E + 255) / 256, 256>>>(src, dst, cursor, csr, E);

    size_t shbytes = (size_t)(2 * WFRAG_FLOATS + TILE_R * AS_STRIDE) * sizeof(float);
    cudaFuncSetAttribute(mma_layer_kernel,
                         cudaFuncAttributeMaxDynamicSharedMemorySize, (int)shbytes);

    int ntiles = (N + TILE_R - 1) / TILE_R;
    int grid = 148;
    if (grid > ntiles) grid = ntiles;

    long long ga_threads = (long long)N * 32;
    unsigned ga_blocks = (unsigned)((ga_threads + 255) / 256);

    for (int l = 0; l < L; l++) {
        gather_kernel<<<ga_blocks, 256>>>((const float4*)h, (float4*)agg, off, csr, N);
        float* dstbuf = (l == L - 1) ? out : h;
        mma_layer_kernel<<<grid, 256, shbytes>>>((const float4*)agg, off,
                                                 Ws + (size_t)l * DD * DD,
                                                 bs + (size_t)l * DD,
                                                 dstbuf, N, ntiles);
    }
}

// round 13
// speedup vs baseline: 2.5843x; 1.1824x over previous
#include <cuda_runtime.h>
#include <cuda_bf16.h>
#include <cstdint>

#define DD 128
#define MAX_N 100000
#define MAX_E 1600000
#define TILE_R 64
#define AS_STRIDE 132      // A tile row stride (floats), float4-aligned

// W fragment table: 8 k-steps(k16) x 16 n-blocks x 32 lanes x float4(wh0,wh1,wl0,wl1)
#define WFRAG_ENTRIES (8 * 16 * 32)       // 4096 float4 = 64KB

// ===================== scratch =====================
__device__ float g_h[(size_t)MAX_N * DD];
__device__ float g_agg[(size_t)MAX_N * DD];
__device__ int   g_degi[MAX_N];
__device__ int   g_off[MAX_N + 1];
__device__ int   g_cursor[MAX_N];
__device__ int   g_bsum[1024];
__device__ int   g_csr[MAX_E];

// ===================== CSR build + embed (proven R6 pieces) =====================
__global__ void embed_kernel(const int* __restrict__ ann,
                             const float4* __restrict__ emb,
                             float4* __restrict__ h,
                             int* __restrict__ degi, int N) {
    int gid = blockIdx.x * blockDim.x + threadIdx.x;
    if (gid < N) degi[gid] = 0;
    int n = gid >> 5;
    int lane = gid & 31;
    if (n >= N) return;
    int a = __ldg(ann + n);
    h[(size_t)n * 32 + lane] = __ldg(emb + (size_t)a * 32 + lane);
}

__global__ void degi_kernel(const int* __restrict__ dst, int* __restrict__ degi, int E) {
    int e = blockIdx.x * blockDim.x + threadIdx.x;
    if (e < E) atomicAdd(degi + dst[e], 1);
}

__global__ void scan1_kernel(const int* __restrict__ degi, int* __restrict__ off,
                             int* __restrict__ bsum, int N) {
    __shared__ int s[256];
    int t = threadIdx.x;
    int i = blockIdx.x * 256 + t;
    int v = (i < N) ? degi[i] : 0;
    s[t] = v;
    __syncthreads();
#pragma unroll
    for (int d = 1; d < 256; d <<= 1) {
        int add = (t >= d) ? s[t - d] : 0;
        __syncthreads();
        s[t] += add;
        __syncthreads();
    }
    if (i < N) off[i] = s[t] - v;
    if (t == 255) bsum[blockIdx.x] = s[255];
}

__global__ void scan23_kernel(int* __restrict__ off, int* __restrict__ cursor,
                              const int* __restrict__ bsum, int N, int E) {
    __shared__ int s[256];
    int t = threadIdx.x;
    int b = blockIdx.x;
    int acc = 0;
    for (int j = t; j < b; j += 256) acc += bsum[j];
    s[t] = acc;
    __syncthreads();
#pragma unroll
    for (int d = 128; d > 0; d >>= 1) {
        if (t < d) s[t] += s[t + d];
        __syncthreads();
    }
    int prefix = s[0];
    int i = b * 256 + t;
    if (i < N) {
        int o = off[i] + prefix;
        off[i] = o;
        cursor[i] = o;
    }
    if (i == 0) off[N] = E;
}

__global__ void place_kernel(const int* __restrict__ src, const int* __restrict__ dst,
                             int* __restrict__ cursor, int* __restrict__ csr, int E) {
    int e = blockIdx.x * blockDim.x + threadIdx.x;
    if (e >= E) return;
    int pos = atomicAdd(cursor + dst[e], 1);
    csr[pos] = src[e];
}

__global__ void gather_kernel(const float4* __restrict__ h,
                              float4* __restrict__ agg,
                              const int* __restrict__ off,
                              const int* __restrict__ csr, int N) {
    int gid = blockIdx.x * blockDim.x + threadIdx.x;
    int n = gid >> 5;
    int lane = gid & 31;
    if (n >= N) return;
    int beg = __ldg(off + n);
    int end = __ldg(off + n + 1);
    float4 acc = __ldg(h + (size_t)n * 32 + lane);
    int i = beg;
    for (; i + 4 <= end; i += 4) {
        int s0 = __ldg(csr + i);
        int s1 = __ldg(csr + i + 1);
        int s2 = __ldg(csr + i + 2);
        int s3 = __ldg(csr + i + 3);
        float4 v0 = __ldg(h + (size_t)s0 * 32 + lane);
        float4 v1 = __ldg(h + (size_t)s1 * 32 + lane);
        float4 v2 = __ldg(h + (size_t)s2 * 32 + lane);
        float4 v3 = __ldg(h + (size_t)s3 * 32 + lane);
        acc.x += v0.x + v1.x + v2.x + v3.x;
        acc.y += v0.y + v1.y + v2.y + v3.y;
        acc.z += v0.z + v1.z + v2.z + v3.z;
        acc.w += v0.w + v1.w + v2.w + v3.w;
    }
    for (; i < end; i++) {
        int s = __ldg(csr + i);
        float4 v = __ldg(h + (size_t)s * 32 + lane);
        acc.x += v.x; acc.y += v.y; acc.z += v.z; acc.w += v.w;
    }
    agg[(size_t)n * 32 + lane] = acc;
}

// ===================== bf16 3-pass mma.sync layer GEMM =====================
// out[r][:] = relu( (agg[r][:] / (deg+1)) @ W + b )
// Split x = xh(bf16) + xl(bf16 of residual); D = ah*wh + ah*wl + al*wh.
// Persistent grid=148; W fragments (wh0,wh1,wl0,wl1) built once; A tiles
// cp.async double-buffered.
// Warp (wid): wm = wid&3 -> rows 16*wm..+15 ; wn = wid>>2 -> cols 64*wn..+63.

#define PACK_BF16X2(r, flo, fhi) \
    asm("cvt.rn.bf16x2.f32 %0, %1, %2;" : "=r"(r) : "f"(fhi), "f"(flo))

#define MMA_BF16(C, A0, A1, A2, A3, B0, B1)                                   \
    asm volatile("mma.sync.aligned.m16n8k16.row.col.f32.bf16.bf16.f32 "       \
                 "{%0,%1,%2,%3}, {%4,%5,%6,%7}, {%8,%9}, {%0,%1,%2,%3};"      \
                 : "+f"((C)[0]), "+f"((C)[1]), "+f"((C)[2]), "+f"((C)[3])     \
                 : "r"(A0), "r"(A1), "r"(A2), "r"(A3), "r"(B0), "r"(B1))

__device__ __forceinline__ void cp_async16(uint32_t dst, const void* src, int sz) {
    asm volatile("cp.async.cg.shared.global [%0], [%1], 16, %2;"
                 :: "r"(dst), "l"(src), "r"(sz) : "memory");
}
#define CP_COMMIT() asm volatile("cp.async.commit_group;" ::: "memory")
#define CP_WAIT0()  asm volatile("cp.async.wait_group 0;" ::: "memory")

__device__ __forceinline__ float bf_hi(uint32_t packed, int hi) {
    uint32_t u = hi ? (packed & 0xFFFF0000u) : (packed << 16);
    return __uint_as_float(u);
}

__global__ __launch_bounds__(256, 1)
void mma_layer_kernel(const float4* __restrict__ agg,
                      const int* __restrict__ off,
                      const float* __restrict__ W,
                      const float* __restrict__ bias,
                      float* __restrict__ out, int N, int ntiles) {
    extern __shared__ float sh[];
    float4* Ff = (float4*)sh;                       // WFRAG_ENTRIES float4
    float* AshB[2];
    AshB[0] = sh + WFRAG_ENTRIES * 4;
    AshB[1] = AshB[0] + TILE_R * AS_STRIDE;

    uint32_t ash_u[2];
    {
        uint32_t a0;
        asm("{ .reg .u64 t; cvta.to.shared.u64 t, %1; cvt.u32.u64 %0, t; }"
            : "=r"(a0) : "l"((const void*)AshB[0]));
        ash_u[0] = a0;
        ash_u[1] = a0 + TILE_R * AS_STRIDE * 4;
    }

    int tid  = threadIdx.x;
    int lane = tid & 31;
    int wid  = tid >> 5;
    int tig  = lane & 3;
    int gr   = lane >> 2;
    int wm   = wid & 3;
    int wn   = wid >> 2;

    // ---- Build W fragments once: entry ((s*16+nblk)*32+lane) ----
    for (int idx = tid; idx < WFRAG_ENTRIES; idx += 256) {
        int l    = idx & 31;
        int nblk = (idx >> 5) & 15;
        int s    = idx >> 9;
        int tg = l & 3, g = l >> 2;
        int k0 = 16 * s + 2 * tg;
        int c  = 8 * nblk + g;
        float w00 = __ldg(W + k0 * DD + c);
        float w01 = __ldg(W + (k0 + 1) * DD + c);
        float w10 = __ldg(W + (k0 + 8) * DD + c);
        float w11 = __ldg(W + (k0 + 9) * DD + c);
        uint32_t wh0, wh1;
        PACK_BF16X2(wh0, w00, w01);
        PACK_BF16X2(wh1, w10, w11);
        float l00 = w00 - bf_hi(wh0, 0);
        float l01 = w01 - bf_hi(wh0, 1);
        float l10 = w10 - bf_hi(wh1, 0);
        float l11 = w11 - bf_hi(wh1, 1);
        uint32_t wl0, wl1;
        PACK_BF16X2(wl0, l00, l01);
        PACK_BF16X2(wl1, l10, l11);
        Ff[idx] = make_float4(__uint_as_float(wh0), __uint_as_float(wh1),
                              __uint_as_float(wl0), __uint_as_float(wl1));
    }

    // ---- Prefetch first A tile ----
    int buf = 0;
    {
        int r0 = blockIdx.x * TILE_R;
#pragma unroll
        for (int j = 0; j < 8; j++) {
            int idx = tid + j * 256;
            int row = idx >> 5;
            int c4  = idx & 31;
            int sz = (r0 + row < N) ? 16 : 0;
            cp_async16(ash_u[0] + (uint32_t)(row * AS_STRIDE + c4 * 4) * 4,
                       agg + (size_t)(r0 + row) * 32 + c4, sz);
        }
        CP_COMMIT();
    }

    for (int tile = blockIdx.x; tile < ntiles; tile += gridDim.x) {
        int r0 = tile * TILE_R;
        CP_WAIT0();
        __syncthreads();                  // A[buf] ready; A[buf^1] fully consumed

        int nt = tile + gridDim.x;
        if (nt < ntiles) {
            int nr0 = nt * TILE_R;
#pragma unroll
            for (int j = 0; j < 8; j++) {
                int idx = tid + j * 256;
                int row = idx >> 5;
                int c4  = idx & 31;
                int sz = (nr0 + row < N) ? 16 : 0;
                cp_async16(ash_u[buf ^ 1] + (uint32_t)(row * AS_STRIDE + c4 * 4) * 4,
                           agg + (size_t)(nr0 + row) * 32 + c4, sz);
            }
            CP_COMMIT();
        }

        float* Ash = AshB[buf];
        float c[8][4];
#pragma unroll
        for (int j = 0; j < 8; j++)
#pragma unroll
            for (int q = 0; q < 4; q++) c[j][q] = 0.0f;

        int ra = (16 * wm + gr) * AS_STRIDE;
        int rb = ra + 8 * AS_STRIDE;

#pragma unroll 2
        for (int s = 0; s < 8; s++) {
            int k0 = 16 * s + 2 * tig;
            float f0 = Ash[ra + k0],     f1 = Ash[ra + k0 + 1];
            float f2 = Ash[rb + k0],     f3 = Ash[rb + k0 + 1];
            float f4 = Ash[ra + k0 + 8], f5 = Ash[ra + k0 + 9];
            float f6 = Ash[rb + k0 + 8], f7 = Ash[rb + k0 + 9];
            uint32_t ah0, ah1, ah2, ah3;
            PACK_BF16X2(ah0, f0, f1);
            PACK_BF16X2(ah1, f2, f3);
            PACK_BF16X2(ah2, f4, f5);
            PACK_BF16X2(ah3, f6, f7);
            uint32_t al0, al1, al2, al3;
            PACK_BF16X2(al0, f0 - bf_hi(ah0, 0), f1 - bf_hi(ah0, 1));
            PACK_BF16X2(al1, f2 - bf_hi(ah1, 0), f3 - bf_hi(ah1, 1));
            PACK_BF16X2(al2, f4 - bf_hi(ah2, 0), f5 - bf_hi(ah2, 1));
            PACK_BF16X2(al3, f6 - bf_hi(ah3, 0), f7 - bf_hi(ah3, 1));
#pragma unroll
            for (int j = 0; j < 8; j++) {
                float4 F = Ff[(s * 16 + wn * 8 + j) * 32 + lane];
                uint32_t wh0 = __float_as_uint(F.x), wh1 = __float_as_uint(F.y);
                uint32_t wl0 = __float_as_uint(F.z), wl1 = __float_as_uint(F.w);
                MMA_BF16(c[j], ah0, ah1, ah2, ah3, wh0, wh1);
                MMA_BF16(c[j], ah0, ah1, ah2, ah3, wl0, wl1);
                MMA_BF16(c[j], al0, al1, al2, al3, wh0, wh1);
            }
        }

        // ---- Epilogue ----
        int rowA = r0 + 16 * wm + gr;
        int rowB = rowA + 8;
        float invA = 0.f, invB = 0.f;
        if (rowA < N)
            invA = 1.0f / (float)(__ldg(off + rowA + 1) - __ldg(off + rowA) + 1);
        if (rowB < N)
            invB = 1.0f / (float)(__ldg(off + rowB + 1) - __ldg(off + rowB) + 1);
#pragma unroll
        for (int j = 0; j < 8; j++) {
            int col = wn * 64 + j * 8 + 2 * tig;
            float2 b2 = __ldg((const float2*)(bias + col));
            if (rowA < N) {
                float2 o;
                o.x = fmaxf(c[j][0] * invA + b2.x, 0.0f);
                o.y = fmaxf(c[j][1] * invA + b2.y, 0.0f);
                *(float2*)(out + (size_t)rowA * DD + col) = o;
            }
            if (rowB < N) {
                float2 o;
                o.x = fmaxf(c[j][2] * invB + b2.x, 0.0f);
                o.y = fmaxf(c[j][3] * invB + b2.y, 0.0f);
                *(float2*)(out + (size_t)rowB * DD + col) = o;
            }
        }
        buf ^= 1;
    }
}

// ---------------------------------------------------------------------------
extern "C" void kernel_launch(void* const* d_in, const int* in_sizes, int n_in,
                              void* d_out, int out_size) {
    const int*   ann = (const int*)d_in[0];
    const int*   src = (const int*)d_in[1];
    const int*   dst = (const int*)d_in[2];
    const float* emb = (const float*)d_in[3];
    const float* Ws  = (const float*)d_in[4];
    const float* bs  = (const float*)d_in[5];

    int N = in_sizes[0];
    int E = in_sizes[1];
    int L = in_sizes[4] / (DD * DD);

    float *h, *agg;
    int *degi, *off, *cursor, *bsum, *csr;
    cudaGetSymbolAddress((void**)&h,      g_h);
    cudaGetSymbolAddress((void**)&agg,    g_agg);
    cudaGetSymbolAddress((void**)&degi,   g_degi);
    cudaGetSymbolAddress((void**)&off,    g_off);
    cudaGetSymbolAddress((void**)&cursor, g_cursor);
    cudaGetSymbolAddress((void**)&bsum,   g_bsum);
    cudaGetSymbolAddress((void**)&csr,    g_csr);
    float* out = (float*)d_out;

    int nb = (N + 255) / 256;

    {
        long long t = (long long)N * 32;
        embed_kernel<<<(unsigned)((t + 255) / 256), 256>>>(ann, (const float4*)emb,
                                                           (float4*)h, degi, N);
    }
    degi_kernel<<<(E + 255) / 256, 256>>>(dst, degi, E);
    scan1_kernel<<<nb, 256>>>(degi, off, bsum, N);
    scan23_kernel<<<nb, 256>>>(off, cursor, bsum, N, E);
    place_kernel<<<(E + 255) / 256, 256>>>(src, dst, cursor, csr, E);

    size_t shbytes = (size_t)WFRAG_ENTRIES * 16 +
                     (size_t)2 * TILE_R * AS_STRIDE * sizeof(float);
    cudaFuncSetAttribute(mma_layer_kernel,
                         cudaFuncAttributeMaxDynamicSharedMemorySize, (int)shbytes);

    int ntiles = (N + TILE_R - 1) / TILE_R;
    int grid = 148;
    if (grid > ntiles) grid = ntiles;

    long long ga_threads = (long long)N * 32;
    unsigned ga_blocks = (unsigned)((ga_threads + 255) / 256);

    for (int l = 0; l < L; l++) {
        gather_kernel<<<ga_blocks, 256>>>((const float4*)h, (float4*)agg, off, csr, N);
        float* dstbuf = (l == L - 1) ? out : h;
        mma_layer_kernel<<<grid, 256, shbytes>>>((const float4*)agg, off,
                                                 Ws + (size_t)l * DD * DD,
                                                 bs + (size_t)l * DD,
                                                 dstbuf, N, ntiles);
    }
}

// round 15
// speedup vs baseline: 2.9674x; 1.1482x over previous
#include <cuda_runtime.h>
#include <cuda_fp16.h>
#include <cuda_bf16.h>
#include <cstdint>

#define DD 128
#define MAX_N 100000
#define MAX_E 1600000
#define TILE_R 64
#define AS_STRIDE 132      // A tile row stride (floats), float4-aligned

// W fragment table: 8 k-steps(k16) x 16 n-blocks x 32 lanes x float4(wh0,wh1,wl0,wl1)
#define WFRAG_ENTRIES (8 * 16 * 32)       // 4096 float4 = 64KB

// ---- bit-cast helpers (missing intrinsics in this toolkit) ----
__device__ __forceinline__ uint32_t h2_to_u32(__half2 h) {
    uint32_t u;
    memcpy(&u, &h, 4);
    return u;
}
__device__ __forceinline__ __half2 u32_to_h2(uint32_t u) {
    __half2 h;
    memcpy(&h, &u, 4);
    return h;
}

// ===================== scratch =====================
__device__ __half g_h[(size_t)MAX_N * DD];     // features in fp16
__device__ float  g_agg[(size_t)MAX_N * DD];   // aggregate in fp32
__device__ int    g_degi[MAX_N];
__device__ int    g_off[MAX_N + 1];
__device__ int    g_cursor[MAX_N];
__device__ int    g_bsum[1024];
__device__ int    g_csr[MAX_E];

// ===================== embed + CSR build =====================
// h[n][:] = fp16(emb[annotation[n]][:])  (warp per node) ; also zeroes degi
__global__ void embed_kernel(const int* __restrict__ ann,
                             const float4* __restrict__ emb,
                             uint2* __restrict__ h,        // 4 halves per lane
                             int* __restrict__ degi, int N) {
    int gid = blockIdx.x * blockDim.x + threadIdx.x;
    if (gid < N) degi[gid] = 0;
    int n = gid >> 5;
    int lane = gid & 31;
    if (n >= N) return;
    int a = __ldg(ann + n);
    float4 v = __ldg(emb + (size_t)a * 32 + lane);
    uint2 u;
    u.x = h2_to_u32(__floats2half2_rn(v.x, v.y));
    u.y = h2_to_u32(__floats2half2_rn(v.z, v.w));
    h[(size_t)n * 32 + lane] = u;
}

__global__ void degi_kernel(const int* __restrict__ dst, int* __restrict__ degi, int E) {
    int e = blockIdx.x * blockDim.x + threadIdx.x;
    if (e < E) atomicAdd(degi + dst[e], 1);
}

__global__ void scan1_kernel(const int* __restrict__ degi, int* __restrict__ off,
                             int* __restrict__ bsum, int N) {
    __shared__ int s[256];
    int t = threadIdx.x;
    int i = blockIdx.x * 256 + t;
    int v = (i < N) ? degi[i] : 0;
    s[t] = v;
    __syncthreads();
#pragma unroll
    for (int d = 1; d < 256; d <<= 1) {
        int add = (t >= d) ? s[t - d] : 0;
        __syncthreads();
        s[t] += add;
        __syncthreads();
    }
    if (i < N) off[i] = s[t] - v;
    if (t == 255) bsum[blockIdx.x] = s[255];
}

__global__ void scan23_kernel(int* __restrict__ off, int* __restrict__ cursor,
                              const int* __restrict__ bsum, int N, int E) {
    __shared__ int s[256];
    int t = threadIdx.x;
    int b = blockIdx.x;
    int acc = 0;
    for (int j = t; j < b; j += 256) acc += bsum[j];
    s[t] = acc;
    __syncthreads();
#pragma unroll
    for (int d = 128; d > 0; d >>= 1) {
        if (t < d) s[t] += s[t + d];
        __syncthreads();
    }
    int prefix = s[0];
    int i = b * 256 + t;
    if (i < N) {
        int o = off[i] + prefix;
        off[i] = o;
        cursor[i] = o;
    }
    if (i == 0) off[N] = E;
}

__global__ void place_kernel(const int* __restrict__ src, const int* __restrict__ dst,
                             int* __restrict__ cursor, int* __restrict__ csr, int E) {
    int e = blockIdx.x * blockDim.x + threadIdx.x;
    if (e >= E) return;
    int pos = atomicAdd(cursor + dst[e], 1);
    csr[pos] = src[e];
}

// ===================== gather (fp16 in, fp32 out) =====================
// agg[n] = h[n] + sum_{s in nbr(n)} h[s]   (warp per node; lane = 4 features)
__global__ void gather_kernel(const uint2* __restrict__ h,
                              float4* __restrict__ agg,
                              const int* __restrict__ off,
                              const int* __restrict__ csr, int N) {
    int gid = blockIdx.x * blockDim.x + threadIdx.x;
    int n = gid >> 5;
    int lane = gid & 31;
    if (n >= N) return;
    int beg = __ldg(off + n);
    int end = __ldg(off + n + 1);

    uint2 su = __ldg(h + (size_t)n * 32 + lane);       // self
    float2 f0 = __half22float2(u32_to_h2(su.x));
    float2 f1 = __half22float2(u32_to_h2(su.y));
    float4 acc = make_float4(f0.x, f0.y, f1.x, f1.y);

    int i = beg;
    for (; i + 4 <= end; i += 4) {
        int s0 = __ldg(csr + i);
        int s1 = __ldg(csr + i + 1);
        int s2 = __ldg(csr + i + 2);
        int s3 = __ldg(csr + i + 3);
        uint2 u0 = __ldg(h + (size_t)s0 * 32 + lane);
        uint2 u1 = __ldg(h + (size_t)s1 * 32 + lane);
        uint2 u2 = __ldg(h + (size_t)s2 * 32 + lane);
        uint2 u3 = __ldg(h + (size_t)s3 * 32 + lane);
        float2 a0 = __half22float2(u32_to_h2(u0.x));
        float2 b0 = __half22float2(u32_to_h2(u0.y));
        float2 a1 = __half22float2(u32_to_h2(u1.x));
        float2 b1 = __half22float2(u32_to_h2(u1.y));
        float2 a2 = __half22float2(u32_to_h2(u2.x));
        float2 b2 = __half22float2(u32_to_h2(u2.y));
        float2 a3 = __half22float2(u32_to_h2(u3.x));
        float2 b3 = __half22float2(u32_to_h2(u3.y));
        acc.x += a0.x + a1.x + a2.x + a3.x;
        acc.y += a0.y + a1.y + a2.y + a3.y;
        acc.z += b0.x + b1.x + b2.x + b3.x;
        acc.w += b0.y + b1.y + b2.y + b3.y;
    }
    for (; i < end; i++) {
        int s = __ldg(csr + i);
        uint2 u = __ldg(h + (size_t)s * 32 + lane);
        float2 a = __half22float2(u32_to_h2(u.x));
        float2 b = __half22float2(u32_to_h2(u.y));
        acc.x += a.x; acc.y += a.y; acc.z += b.x; acc.w += b.y;
    }
    agg[(size_t)n * 32 + lane] = acc;
}

// ===================== bf16 3-pass mma.sync layer GEMM =====================
#define PACK_BF16X2(r, flo, fhi) \
    asm("cvt.rn.bf16x2.f32 %0, %1, %2;" : "=r"(r) : "f"(fhi), "f"(flo))

#define MMA_BF16(C, A0, A1, A2, A3, B0, B1)                                   \
    asm volatile("mma.sync.aligned.m16n8k16.row.col.f32.bf16.bf16.f32 "       \
                 "{%0,%1,%2,%3}, {%4,%5,%6,%7}, {%8,%9}, {%0,%1,%2,%3};"      \
                 : "+f"((C)[0]), "+f"((C)[1]), "+f"((C)[2]), "+f"((C)[3])     \
                 : "r"(A0), "r"(A1), "r"(A2), "r"(A3), "r"(B0), "r"(B1))

__device__ __forceinline__ void cp_async16(uint32_t dst, const void* src, int sz) {
    asm volatile("cp.async.cg.shared.global [%0], [%1], 16, %2;"
                 :: "r"(dst), "l"(src), "r"(sz) : "memory");
}
#define CP_COMMIT() asm volatile("cp.async.commit_group;" ::: "memory")
#define CP_WAIT0()  asm volatile("cp.async.wait_group 0;" ::: "memory")

__device__ __forceinline__ float bf_hi(uint32_t packed, int hi) {
    uint32_t u = hi ? (packed & 0xFFFF0000u) : (packed << 16);
    return __uint_as_float(u);
}

// write_half: intermediate layers write fp16 h; final layer writes fp32 out
__global__ __launch_bounds__(256, 1)
void mma_layer_kernel(const float4* __restrict__ agg,
                      const int* __restrict__ off,
                      const float* __restrict__ W,
                      const float* __restrict__ bias,
                      float* __restrict__ outf,
                      __half* __restrict__ outh,
                      int write_half, int N, int ntiles) {
    extern __shared__ float sh[];
    float4* Ff = (float4*)sh;
    float* AshB[2];
    AshB[0] = sh + WFRAG_ENTRIES * 4;
    AshB[1] = AshB[0] + TILE_R * AS_STRIDE;

    uint32_t ash_u[2];
    {
        uint32_t a0;
        asm("{ .reg .u64 t; cvta.to.shared.u64 t, %1; cvt.u32.u64 %0, t; }"
            : "=r"(a0) : "l"((const void*)AshB[0]));
        ash_u[0] = a0;
        ash_u[1] = a0 + TILE_R * AS_STRIDE * 4;
    }

    int tid  = threadIdx.x;
    int lane = tid & 31;
    int wid  = tid >> 5;
    int tig  = lane & 3;
    int gr   = lane >> 2;
    int wm   = wid & 3;
    int wn   = wid >> 2;

    // ---- Build W fragments once ----
    for (int idx = tid; idx < WFRAG_ENTRIES; idx += 256) {
        int l    = idx & 31;
        int nblk = (idx >> 5) & 15;
        int s    = idx >> 9;
        int tg = l & 3, g = l >> 2;
        int k0 = 16 * s + 2 * tg;
        int c  = 8 * nblk + g;
        float w00 = __ldg(W + k0 * DD + c);
        float w01 = __ldg(W + (k0 + 1) * DD + c);
        float w10 = __ldg(W + (k0 + 8) * DD + c);
        float w11 = __ldg(W + (k0 + 9) * DD + c);
        uint32_t wh0, wh1;
        PACK_BF16X2(wh0, w00, w01);
        PACK_BF16X2(wh1, w10, w11);
        float l00 = w00 - bf_hi(wh0, 0);
        float l01 = w01 - bf_hi(wh0, 1);
        float l10 = w10 - bf_hi(wh1, 0);
        float l11 = w11 - bf_hi(wh1, 1);
        uint32_t wl0, wl1;
        PACK_BF16X2(wl0, l00, l01);
        PACK_BF16X2(wl1, l10, l11);
        Ff[idx] = make_float4(__uint_as_float(wh0), __uint_as_float(wh1),
                              __uint_as_float(wl0), __uint_as_float(wl1));
    }

    // ---- Prefetch first A tile ----
    int buf = 0;
    {
        int r0 = blockIdx.x * TILE_R;
#pragma unroll
        for (int j = 0; j < 8; j++) {
            int idx = tid + j * 256;
            int row = idx >> 5;
            int c4  = idx & 31;
            int sz = (r0 + row < N) ? 16 : 0;
            cp_async16(ash_u[0] + (uint32_t)(row * AS_STRIDE + c4 * 4) * 4,
                       agg + (size_t)(r0 + row) * 32 + c4, sz);
        }
        CP_COMMIT();
    }

    for (int tile = blockIdx.x; tile < ntiles; tile += gridDim.x) {
        int r0 = tile * TILE_R;
        CP_WAIT0();
        __syncthreads();

        int nt = tile + gridDim.x;
        if (nt < ntiles) {
            int nr0 = nt * TILE_R;
#pragma unroll
            for (int j = 0; j < 8; j++) {
                int idx = tid + j * 256;
                int row = idx >> 5;
                int c4  = idx & 31;
                int sz = (nr0 + row < N) ? 16 : 0;
                cp_async16(ash_u[buf ^ 1] + (uint32_t)(row * AS_STRIDE + c4 * 4) * 4,
                           agg + (size_t)(nr0 + row) * 32 + c4, sz);
            }
            CP_COMMIT();
        }

        float* Ash = AshB[buf];
        float c[8][4];
#pragma unroll
        for (int j = 0; j < 8; j++)
#pragma unroll
            for (int q = 0; q < 4; q++) c[j][q] = 0.0f;

        int ra = (16 * wm + gr) * AS_STRIDE;
        int rb = ra + 8 * AS_STRIDE;

#pragma unroll 2
        for (int s = 0; s < 8; s++) {
            int k0 = 16 * s + 2 * tig;
            float f0 = Ash[ra + k0],     f1 = Ash[ra + k0 + 1];
            float f2 = Ash[rb + k0],     f3 = Ash[rb + k0 + 1];
            float f4 = Ash[ra + k0 + 8], f5 = Ash[ra + k0 + 9];
            float f6 = Ash[rb + k0 + 8], f7 = Ash[rb + k0 + 9];
            uint32_t ah0, ah1, ah2, ah3;
            PACK_BF16X2(ah0, f0, f1);
            PACK_BF16X2(ah1, f2, f3);
            PACK_BF16X2(ah2, f4, f5);
            PACK_BF16X2(ah3, f6, f7);
            uint32_t al0, al1, al2, al3;
            PACK_BF16X2(al0, f0 - bf_hi(ah0, 0), f1 - bf_hi(ah0, 1));
            PACK_BF16X2(al1, f2 - bf_hi(ah1, 0), f3 - bf_hi(ah1, 1));
            PACK_BF16X2(al2, f4 - bf_hi(ah2, 0), f5 - bf_hi(ah2, 1));
            PACK_BF16X2(al3, f6 - bf_hi(ah3, 0), f7 - bf_hi(ah3, 1));
#pragma unroll
            for (int j = 0; j < 8; j++) {
                float4 F = Ff[(s * 16 + wn * 8 + j) * 32 + lane];
                uint32_t wh0 = __float_as_uint(F.x), wh1 = __float_as_uint(F.y);
                uint32_t wl0 = __float_as_uint(F.z), wl1 = __float_as_uint(F.w);
                MMA_BF16(c[j], ah0, ah1, ah2, ah3, wh0, wh1);
                MMA_BF16(c[j], ah0, ah1, ah2, ah3, wl0, wl1);
                MMA_BF16(c[j], al0, al1, al2, al3, wh0, wh1);
            }
        }

        // ---- Epilogue ----
        int rowA = r0 + 16 * wm + gr;
        int rowB = rowA + 8;
        float invA = 0.f, invB = 0.f;
        if (rowA < N)
            invA = 1.0f / (float)(__ldg(off + rowA + 1) - __ldg(off + rowA) + 1);
        if (rowB < N)
            invB = 1.0f / (float)(__ldg(off + rowB + 1) - __ldg(off + rowB) + 1);
#pragma unroll
        for (int j = 0; j < 8; j++) {
            int col = wn * 64 + j * 8 + 2 * tig;
            float2 b2 = __ldg((const float2*)(bias + col));
            float2 oA, oB;
            oA.x = fmaxf(c[j][0] * invA + b2.x, 0.0f);
            oA.y = fmaxf(c[j][1] * invA + b2.y, 0.0f);
            oB.x = fmaxf(c[j][2] * invB + b2.x, 0.0f);
            oB.y = fmaxf(c[j][3] * invB + b2.y, 0.0f);
            if (write_half) {
                if (rowA < N) {
                    __half2 p = __floats2half2_rn(oA.x, oA.y);
                    *(__half2*)(outh + (size_t)rowA * DD + col) = p;
                }
                if (rowB < N) {
                    __half2 p = __floats2half2_rn(oB.x, oB.y);
                    *(__half2*)(outh + (size_t)rowB * DD + col) = p;
                }
            } else {
                if (rowA < N) *(float2*)(outf + (size_t)rowA * DD + col) = oA;
                if (rowB < N) *(float2*)(outf + (size_t)rowB * DD + col) = oB;
            }
        }
        buf ^= 1;
    }
}

// ---------------------------------------------------------------------------
extern "C" void kernel_launch(void* const* d_in, const int* in_sizes, int n_in,
                              void* d_out, int out_size) {
    const int*   ann = (const int*)d_in[0];
    const int*   src = (const int*)d_in[1];
    const int*   dst = (const int*)d_in[2];
    const float* emb = (const float*)d_in[3];
    const float* Ws  = (const float*)d_in[4];
    const float* bs  = (const float*)d_in[5];

    int N = in_sizes[0];
    int E = in_sizes[1];
    int L = in_sizes[4] / (DD * DD);

    __half* h;
    float* agg;
    int *degi, *off, *cursor, *bsum, *csr;
    cudaGetSymbolAddress((void**)&h,      g_h);
    cudaGetSymbolAddress((void**)&agg,    g_agg);
    cudaGetSymbolAddress((void**)&degi,   g_degi);
    cudaGetSymbolAddress((void**)&off,    g_off);
    cudaGetSymbolAddress((void**)&cursor, g_cursor);
    cudaGetSymbolAddress((void**)&bsum,   g_bsum);
    cudaGetSymbolAddress((void**)&csr,    g_csr);
    float* out = (float*)d_out;

    int nb = (N + 255) / 256;

    {
        long long t = (long long)N * 32;
        embed_kernel<<<(unsigned)((t + 255) / 256), 256>>>(ann, (const float4*)emb,
                                                           (uint2*)h, degi, N);
    }
    degi_kernel<<<(E + 255) / 256, 256>>>(dst, degi, E);
    scan1_kernel<<<nb, 256>>>(degi, off, bsum, N);
    scan23_kernel<<<nb, 256>>>(off, cursor, bsum, N, E);
    place_kernel<<<(E + 255) / 256, 256>>>(src, dst, cursor, csr, E);

    size_t shbytes = (size_t)WFRAG_ENTRIES * 16 +
                     (size_t)2 * TILE_R * AS_STRIDE * sizeof(float);
    cudaFuncSetAttribute(mma_layer_kernel,
                         cudaFuncAttributeMaxDynamicSharedMemorySize, (int)shbytes);

    int ntiles = (N + TILE_R - 1) / TILE_R;
    int grid = 148;
    if (grid > ntiles) grid = ntiles;

    long long ga_threads = (long long)N * 32;
    unsigned ga_blocks = (unsigned)((ga_threads + 255) / 256);

    for (int l = 0; l < L; l++) {
        gather_kernel<<<ga_blocks, 256>>>((const uint2*)h, (float4*)agg, off, csr, N);
        int last = (l == L - 1);
        mma_layer_kernel<<<grid, 256, shbytes>>>((const float4*)agg, off,
                                                 Ws + (size_t)l * DD * DD,
                                                 bs + (size_t)l * DD,
                                                 last ? out : nullptr,
                                                 last ? nullptr : h,
                                                 !last, N, ntiles);
    }
}